// round 5
// baseline (speedup 1.0000x reference)
#include <cuda_runtime.h>

// ---- problem constants ----
#define Gg      180
#define NATOMS  64
#define NRAD    8
#define NANG    16
#define RMAXI   13
#define BDIM    27
#define NCELLS  (BDIM*BDIM*BDIM)   // 19683
#define CSPLIT  5
#define NTH     64
#define CAPW    2048
#define NHALF   2
#define NLOC    4                  // radial outputs per block

#define A_F   (0.2f)
#define RO_F  (2.5f)
#define VCELL_F ((float)((36.0/180.0)*(36.0/180.0)*(36.0/180.0)))

// scratch (static __device__: no allocation)
__device__ float g_part[NATOMS * NHALF * CSPLIT * 64];
__device__ int   g_cnt[NATOMS * NHALF];     // self-resetting arrival counters

__global__ __launch_bounds__(NTH, 6)
void proj_kernel(const float* __restrict__ rho, const float* __restrict__ pos,
                 const float* __restrict__ W, float* __restrict__ out)
{
    const int split = blockIdx.x;
    const int atom  = blockIdx.y;
    const int nh    = blockIdx.z;
    const int tid   = threadIdx.x;
    const int warp  = tid >> 5;
    const int lane  = tid & 31;

    __shared__ float sOfs[3][BDIM];
    __shared__ int   sIdx[3][BDIM];
    __shared__ unsigned short slist[2 * CAPW];
    __shared__ int   scnt[2];
    __shared__ int   s_old;
    __shared__ float sred[NTH][65];

    // ---------- per-dimension stencil setup ----------
    if (tid < 3 * BDIM - 64 + 64) { }   // (no-op; keep layout simple)
    {
        // 81 work items over 64 threads: two passes
        for (int w = tid; w < 3 * BDIM; w += NTH) {
            int dim = w / BDIM;
            int o   = w - dim * BDIM;
            int off = o - RMAXI;
            float p  = pos[atom * 3 + dim];
            float cm = rintf(p / A_F);                 // round-half-even == jnp.round
            float dr = __fadd_rn(p, -__fmul_rn(A_F, cm));
            int ci = (int)cm + off;
            if (ci < 0)   ci += Gg;
            if (ci >= Gg) ci -= Gg;
            sIdx[dim][o] = ci;
            sOfs[dim][o] = __fadd_rn(__fmul_rn((float)off, A_F), -dr);
        }
    }

    // W rows for this n-half into registers
    float Wr[NLOC][NRAD];
    #pragma unroll
    for (int nn = 0; nn < NLOC; ++nn)
        #pragma unroll
        for (int m = 0; m < NRAD; ++m)
            Wr[nn][m] = __ldg(&W[(nh * NLOC + nn) * NRAD + m]);

    __syncthreads();

    // ---------- phase 1: per-warp deterministic compaction ----------
    const float ro2 = RO_F * RO_F;
    const int c0 = (split * NCELLS) / CSPLIT;
    const int c1 = ((split + 1) * NCELLS) / CSPLIT;
    const int nit = (c1 - c0 + NTH - 1) / NTH;
    int wbase = 0;
    #pragma unroll 1
    for (int it = 0; it < nit; ++it) {
        int c = c0 + it * NTH + tid;
        bool valid = c < c1;
        unsigned cc = valid ? (unsigned)c : 0u;
        unsigned i = cc / 729u;
        unsigned r = cc - i * 729u;
        unsigned j = r / 27u;
        unsigned k = r - j * 27u;
        float x = sOfs[0][i], y = sOfs[1][j], z = sOfs[2][k];
        float r2 = x * x + y * y + z * z;
        bool pred = valid && (r2 < ro2);
        unsigned mask = __ballot_sync(0xFFFFFFFFu, pred);
        if (pred) {
            int p = wbase + __popc(mask & ((1u << lane) - 1u));
            if (p < CAPW)
                slist[warp * CAPW + p] = (unsigned short)((i << 10) | (j << 5) | k);
        }
        wbase += __popc(mask);
    }
    if (lane == 0) scnt[warp] = (wbase < CAPW) ? wbase : CAPW;
    __syncthreads();

    // ---------- phase 2: dense accumulation in orthonormal radial basis ----------
    float acc[NLOC * NANG];                 // acc[nn*16 + lm]
    #pragma unroll
    for (int q = 0; q < NLOC * NANG; ++q) acc[q] = 0.0f;

    #pragma unroll 1
    for (int seg = 0; seg < 2; ++seg) {
        const int cnt = scnt[seg];
        const unsigned short* lst = &slist[seg * CAPW];
        int idx = tid;
        if (idx >= cnt) continue;

        unsigned cell = lst[idx];
        {
            int i = cell >> 10, j = (cell >> 5) & 31, k = cell & 31;
            (void)i; (void)j; (void)k;
        }
        int i0 = cell >> 10, j0 = (cell >> 5) & 31, k0 = cell & 31;
        float rv = __ldg(&rho[(sIdx[0][i0] * Gg + sIdx[1][j0]) * Gg + sIdx[2][k0]]);

        #pragma unroll 1
        while (true) {
            // prefetch next cell + density
            int nidx = idx + NTH;
            bool more = nidx < cnt;
            unsigned ncell = 0; float nrv = 0.0f;
            if (more) {
                ncell = lst[nidx];
                int ni = ncell >> 10, nj = (ncell >> 5) & 31, nk = ncell & 31;
                nrv = __ldg(&rho[(sIdx[0][ni] * Gg + sIdx[1][nj]) * Gg + sIdx[2][nk]]);
            }

            int i = cell >> 10, j = (cell >> 5) & 31, k = cell & 31;
            float x = sOfs[0][i], y = sOfs[1][j], z = sOfs[2][k];
            float r2 = x * x + y * y + z * z;
            float rinv = rsqrtf(fmaxf(r2, 1e-24f));
            float R  = r2 * rinv;
            float b  = RO_F - R;

            // radial: u_n = sum_m W[n,m] * phi_m * rho, phi_m = r^2 b^{m+2}
            float t  = r2 * (b * b) * rv;
            float u0 = 0.0f, u1 = 0.0f, u2 = 0.0f, u3 = 0.0f;
            #pragma unroll
            for (int m = 0; m < NRAD; ++m) {
                u0 = fmaf(Wr[0][m], t, u0);
                u1 = fmaf(Wr[1][m], t, u1);
                u2 = fmaf(Wr[2][m], t, u2);
                u3 = fmaf(Wr[3][m], t, u3);
                if (m < NRAD - 1) t *= b;
            }

            // angular: real SH l=0..3 on unit vector
            float ux = x * rinv, uy = y * rinv, uz = z * rinv;
            float ux2 = ux * ux, uy2 = uy * uy, uz2 = uz * uz;
            float Y[NANG];
            Y[0]  = 0.28209479177387814f;
            Y[1]  = 0.4886025119029199f * uy;
            Y[2]  = 0.4886025119029199f * uz;
            Y[3]  = 0.4886025119029199f * ux;
            Y[4]  = 0.5462742152960396f * (2.0f * ux * uy);
            Y[5]  = 1.0925484305920792f * (uy * uz);
            Y[6]  = 0.31539156525252005f * (3.0f * uz2 - 1.0f);
            Y[7]  = 1.0925484305920792f * (ux * uz);
            Y[8]  = 0.5462742152960396f * (ux2 - uy2);
            Y[9]  = 0.5900435899266435f * uy * (3.0f * ux2 - uy2);
            Y[10] = 1.445305721320277f  * (2.0f * ux * uy * uz);
            Y[11] = 0.4570457994644658f * uy * (5.0f * uz2 - 1.0f);
            Y[12] = 0.3731763325901154f * uz * (5.0f * uz2 - 3.0f);
            Y[13] = 0.4570457994644658f * ux * (5.0f * uz2 - 1.0f);
            Y[14] = 1.445305721320277f  * (ux2 - uy2) * uz;
            Y[15] = 0.5900435899266435f * ux * (ux2 - 3.0f * uy2);

            #pragma unroll
            for (int lm = 0; lm < NANG; ++lm) {
                float yv = Y[lm];
                acc[lm]      = fmaf(u0, yv, acc[lm]);
                acc[16 + lm] = fmaf(u1, yv, acc[16 + lm]);
                acc[32 + lm] = fmaf(u2, yv, acc[32 + lm]);
                acc[48 + lm] = fmaf(u3, yv, acc[48 + lm]);
            }

            if (!more) break;
            idx = nidx; cell = ncell; rv = nrv;
        }
    }

    // ---------- block reduction via shared transpose ----------
    #pragma unroll
    for (int q = 0; q < NLOC * NANG; ++q) sred[tid][q] = acc[q];
    __syncthreads();
    {
        float s = 0.0f;
        #pragma unroll
        for (int t = 0; t < NTH; ++t) s += sred[t][tid];
        g_part[((atom * NHALF + nh) * CSPLIT + split) * 64 + tid] = s;
    }

    // ---------- last-block-per-(atom,nhalf) finalization ----------
    __threadfence();
    if (tid == 0) s_old = atomicAdd(&g_cnt[atom * NHALF + nh], 1);
    __syncthreads();
    if (s_old == CSPLIT - 1) {
        __threadfence();
        float s = 0.0f;
        #pragma unroll
        for (int sp = 0; sp < CSPLIT; ++sp)
            s += g_part[((atom * NHALF + nh) * CSPLIT + sp) * 64 + tid];
        out[atom * 128 + nh * 64 + tid] = s * VCELL_F;
        if (tid == 0) g_cnt[atom * NHALF + nh] = 0;   // reset for graph replay
    }
}

extern "C" void kernel_launch(void* const* d_in, const int* in_sizes, int n_in,
                              void* d_out, int out_size)
{
    const float* rho = (const float*)d_in[0];   // [180,180,180]
    const float* pos = (const float*)d_in[1];   // [64,3]
    const float* W   = (const float*)d_in[2];   // [8,8]
    float* out = (float*)d_out;                 // [64,128]

    dim3 grid(CSPLIT, NATOMS, NHALF);           // 5 x 64 x 2 = 640 blocks
    proj_kernel<<<grid, NTH>>>(rho, pos, W, out);
}